// round 15
// baseline (speedup 1.0000x reference)
#include <cuda_runtime.h>
#include <math.h>

typedef unsigned long long ull;

// Shapes
#define NROWS 4096
#define RPB   16           // rows per block
#define CHUNKS 37          // 37 x 32 = 1184 k (1024 news | 158 price | 2 pad)
#define OFF_PRED 0
#define OFF_RW1  (NROWS)
#define OFF_HID  (NROWS + NROWS*64)
#define OFF_TK   (NROWS + 2*NROWS*64)
#define OFF_RW2  (NROWS + 2*NROWS*64 + NROWS*2)

// ---------------------------------------------------------------------------
// helpers
// ---------------------------------------------------------------------------
__device__ __forceinline__ ull pk2(float v) {
    ull r; asm("mov.b64 %0, {%1,%1};" : "=l"(r) : "f"(v)); return r;
}
__device__ __forceinline__ void fma2(ull& d, ull a, ull b) {
    asm("fma.rn.f32x2 %0, %1, %2, %0;" : "+l"(d) : "l"(a), "l"(b));
}
__device__ __forceinline__ void add2(ull& d, ull a) {
    asm("add.rn.f32x2 %0, %0, %1;" : "+l"(d) : "l"(a));
}
__device__ __forceinline__ void unpk2(ull v, float& lo, float& hi) {
    asm("mov.b64 {%0,%1}, %2;" : "=f"(lo), "=f"(hi) : "l"(v));
}
__device__ __forceinline__ unsigned s2u(const void* p) {
    unsigned a;
    asm("{ .reg .u64 t; cvta.to.shared.u64 t, %1; cvt.u32.u64 %0, t; }"
        : "=r"(a) : "l"(p));
    return a;
}
#define CPA16(dst, src) \
    asm volatile("cp.async.ca.shared.global [%0], [%1], 16;" \
                 :: "r"(dst), "l"(src))
#define CPA_COMMIT()  asm volatile("cp.async.commit_group;")
#define CPA_WAIT0()   asm volatile("cp.async.wait_group 0;" ::: "memory")
union F4U { float4 f; ull u[2]; };

// ---------------------------------------------------------------------------
// Single fused kernel. 256 blocks x 256 threads, 16 rows/block, 2 CTAs/SM.
// Phase 1: aggregation (LDG.128, t-split, 5-slot ring issued 4 sub-batches
//          ahead ~ >600 cyc window) overlapped with k-split-2 router GEMM.
// Phase 2 (smem-aliased): cross-warp combine, tanh, gate GEMM, top2, experts.
// ---------------------------------------------------------------------------
__global__ __launch_bounds__(256, 2) void k_all(
    const float* __restrict__ price, const float* __restrict__ news,
    const float* __restrict__ mask,  const float* __restrict__ rW,
    const float* __restrict__ rb,
    const float* __restrict__ gW,  const float* __restrict__ gb,
    const float* __restrict__ eW,  const float* __restrict__ eb,
    const float* __restrict__ wq,  const float* __restrict__ wqb,
    const float* __restrict__ wk,  const float* __restrict__ wkb,
    const float* __restrict__ wv,  const float* __restrict__ wvb,
    const float* __restrict__ wo,  const float* __restrict__ wob,
    float* __restrict__ out)
{
    __shared__ __align__(16) float Ws[2][32][128];   // 32 KB (aliased later)
    __shared__ __align__(16) float Xs[2][32][20];    // 5 KB (pitch 20)
    __shared__ __align__(16) float mw[RPB][33];      // mask weights
    __shared__ __align__(16) float4 Ps[RPB][8];      // agg t-split partials

    // phase-2 aliases inside Ws
    float* hP   = &Ws[0][0][0];                      // h_s  [16][132]
    float* hidP = hP + 16 * 132;                     // hid_s[16][68]
    ull*   QsP  = (ull*)((char*)&Ws[0][0][0] + 16384);  // [128][8] GEMM parts
#define HSE(r,c)  hP[(r) * 132 + (c)]
#define HIDE(r,c) hidP[(r) * 68 + (c)]
#define QS(t,i)   QsP[(t) * 8 + (i)]

    const int tid  = threadIdx.x;
    const int lane = tid & 31;
    const int wid  = tid >> 5;
    const int row0 = blockIdx.x * RPB;

    // ---- mask weights -------------------------------------------------------
    if (tid < RPB) {
        const float* mr = mask + (size_t)(row0 + tid) * 32;
        float s = 0.f;
#pragma unroll
        for (int t = 0; t < 32; ++t) s += __ldg(mr + t);
        float inv = 1.f / fmaxf(s, 1e-6f);
#pragma unroll
        for (int t = 0; t < 32; ++t) mw[tid][t] = __ldg(mr + t) * inv;
    }

    // aggregation mapping: thread -> t-half th, row ar, col-quad aj
    const int th = tid >> 7;            // 0: t 0-15, 1: t 16-31
    const int ar = (tid >> 3) & 15;
    const int aj = tid & 7;
    const float* nbase = news  + ((size_t)(row0 + ar) * 32 + th * 16) * 1024
                               + aj * 4;
    const float* pbase = price + ((size_t)(row0 + ar) * 32 + th * 16) * 158;
    // W loader mapping (cp.async)
    const int wkk = tid >> 3;
    const int wcc = (tid & 7) * 16;
    unsigned wdst[2];
    wdst[0] = s2u(&Ws[0][wkk][wcc]);
    wdst[1] = s2u(&Ws[1][wkk][wcc]);
    // GEMM mapping: ks = k-half, warp = 8 rows x 64 cols
    const int ks = wid >> 2;                         // 0 or 1
    const int hw = wid & 3;
    const int rq = (hw & 1) << 3;                    // 0 or 8
    const int cc = ((hw >> 1) << 6) + (lane << 1);   // col pair base

    // acc[p][c]: rows (rq+2p, rq+2p+1) packed, col cc+c
    ull acc[4][2];
#pragma unroll
    for (int p = 0; p < 4; ++p) { acc[p][0] = 0ull; acc[p][1] = 0ull; }

    // ---- W chunk 0 via cp.async --------------------------------------------
    {
        const float* wp = rW + (size_t)(wkk + 158) * 128 + wcc;
#pragma unroll
        for (int q = 0; q < 4; ++q) CPA16(wdst[0] + 16 * q, wp + 4 * q);
        CPA_COMMIT();
    }
    __syncthreads();   // mask weights visible

    // ---- prologue: aggregate + store chunk 0 (news) ------------------------
    {
        float4 a = make_float4(0.f, 0.f, 0.f, 0.f);
#pragma unroll
        for (int t = 0; t < 16; ++t) {
            float4 nv = *(const float4*)(nbase + (size_t)t * 1024);
            float w = mw[ar][th * 16 + t];
            a.x = fmaf(w, nv.x, a.x); a.y = fmaf(w, nv.y, a.y);
            a.z = fmaf(w, nv.z, a.z); a.w = fmaf(w, nv.w, a.w);
        }
        if (th == 1) Ps[ar][aj] = a;
        __syncthreads();
        if (th == 0) {
            float4 p = Ps[ar][aj];
            Xs[0][aj * 4 + 0][ar] = a.x + p.x;
            Xs[0][aj * 4 + 1][ar] = a.y + p.y;
            Xs[0][aj * 4 + 2][ar] = a.z + p.z;
            Xs[0][aj * 4 + 3][ar] = a.w + p.w;
        }
    }
    CPA_WAIT0();
    __syncthreads();

    // ---- main loop ----------------------------------------------------------
#pragma unroll 1
    for (int c = 0; c < CHUNKS; ++c) {
        const int  s      = c & 1;
        const bool more   = (c + 1 < CHUNKS);
        const bool isNews = (c + 1 < 32);
        const int  kb     = (c + 1) * 32;
        const int  d0     = kb - 1024 + aj * 4;

        // stage W chunk c+1 via cp.async
        if (more) {
            int k = kb + wkk;
            if (k < 1182) {
                int wr = (k < 1024) ? (k + 158) : (k - 1024);
                const float* wp = rW + (size_t)wr * 128 + wcc;
#pragma unroll
                for (int q = 0; q < 4; ++q)
                    CPA16(wdst[1 - s] + 16 * q, wp + 4 * q);
            } else {
                float4 z = make_float4(0.f, 0.f, 0.f, 0.f);
#pragma unroll
                for (int q = 0; q < 4; ++q)
                    *(float4*)&Ws[1 - s][wkk][wcc + 4 * q] = z;
            }
            CPA_COMMIT();
        }

        // 5-slot ring of 2-t sub-batches, issued 4 sub-batches ahead
        float4 nv[5][2];
#pragma unroll
        for (int pb = 0; pb < 4; ++pb) {
            if (more) {
                if (isNews) {
#pragma unroll
                    for (int t2 = 0; t2 < 2; ++t2)
                        nv[pb][t2] = *(const float4*)(nbase +
                                     (size_t)(pb * 2 + t2) * 1024 + kb);
                } else {
#pragma unroll
                    for (int t2 = 0; t2 < 2; ++t2) {
                        const float* pr = pbase + (size_t)(pb * 2 + t2) * 158;
                        nv[pb][t2].x = (d0 + 0 < 158) ? __ldg(pr + d0 + 0) : 0.f;
                        nv[pb][t2].y = (d0 + 1 < 158) ? __ldg(pr + d0 + 1) : 0.f;
                        nv[pb][t2].z = (d0 + 2 < 158) ? __ldg(pr + d0 + 2) : 0.f;
                        nv[pb][t2].w = (d0 + 3 < 158) ? __ldg(pr + d0 + 3) : 0.f;
                    }
                }
            }
        }

        float4 a = make_float4(0.f, 0.f, 0.f, 0.f);

#pragma unroll
        for (int sb = 0; sb < 8; ++sb) {
            // issue sub-batch sb+4 into ring slot (sb+4)%5
            if (more && sb + 4 < 8) {
                float4* nxt = nv[(sb + 4) % 5];
                if (isNews) {
#pragma unroll
                    for (int t2 = 0; t2 < 2; ++t2)
                        nxt[t2] = *(const float4*)(nbase +
                                  (size_t)((sb + 4) * 2 + t2) * 1024 + kb);
                } else {
#pragma unroll
                    for (int t2 = 0; t2 < 2; ++t2) {
                        const float* pr = pbase +
                            (size_t)((sb + 4) * 2 + t2) * 158;
                        nxt[t2].x = (d0 + 0 < 158) ? __ldg(pr + d0 + 0) : 0.f;
                        nxt[t2].y = (d0 + 1 < 158) ? __ldg(pr + d0 + 1) : 0.f;
                        nxt[t2].z = (d0 + 2 < 158) ? __ldg(pr + d0 + 2) : 0.f;
                        nxt[t2].w = (d0 + 3 < 158) ? __ldg(pr + d0 + 3) : 0.f;
                    }
                }
            }
            // GEMM: this warp's 2 k's of this sub-batch window
#pragma unroll
            for (int kk = 0; kk < 2; ++kk) {
                const int k = sb * 4 + ks * 2 + kk;
                F4U x0, x1;
                x0.f = *(const float4*)&Xs[s][k][rq];        // rows rq..rq+3
                x1.f = *(const float4*)&Xs[s][k][rq + 4];    // rows rq+4..rq+7
                float2 wv2 = *(const float2*)&Ws[s][k][cc];  // 2 cols
                ull w0 = pk2(wv2.x), w1 = pk2(wv2.y);
                fma2(acc[0][0], x0.u[0], w0); fma2(acc[0][1], x0.u[0], w1);
                fma2(acc[1][0], x0.u[1], w0); fma2(acc[1][1], x0.u[1], w1);
                fma2(acc[2][0], x1.u[0], w0); fma2(acc[2][1], x1.u[0], w1);
                fma2(acc[3][0], x1.u[1], w0); fma2(acc[3][1], x1.u[1], w1);
            }
            // fold sub-batch sb from ring slot sb%5
            if (more) {
                float4* cur = nv[sb % 5];
                if (isNews) {
#pragma unroll
                    for (int t2 = 0; t2 < 2; ++t2) {
                        float w = mw[ar][th * 16 + sb * 2 + t2];
                        a.x = fmaf(w, cur[t2].x, a.x);
                        a.y = fmaf(w, cur[t2].y, a.y);
                        a.z = fmaf(w, cur[t2].z, a.z);
                        a.w = fmaf(w, cur[t2].w, a.w);
                    }
                } else {
#pragma unroll
                    for (int t2 = 0; t2 < 2; ++t2) {
                        a.x += cur[t2].x; a.y += cur[t2].y;
                        a.z += cur[t2].z; a.w += cur[t2].w;
                    }
                }
            }
        }

        if (more) {
            if (th == 1) Ps[ar][aj] = a;
            __syncthreads();
            if (th == 0) {
                const float sc = isNews ? 1.f : (1.f / 32.f);
                float4 p = Ps[ar][aj];
                Xs[1 - s][aj * 4 + 0][ar] = (a.x + p.x) * sc;
                Xs[1 - s][aj * 4 + 1][ar] = (a.y + p.y) * sc;
                Xs[1 - s][aj * 4 + 2][ar] = (a.z + p.z) * sc;
                Xs[1 - s][aj * 4 + 3][ar] = (a.w + p.w) * sc;
            }
            CPA_WAIT0();
        }
        __syncthreads();
    }

    // ---- cross-warp k-combine, bias + tanh -> h_s ---------------------------
    if (ks == 1) {
#pragma unroll
        for (int p = 0; p < 4; ++p) {
            QS(tid - 128, 2 * p)     = acc[p][0];
            QS(tid - 128, 2 * p + 1) = acc[p][1];
        }
    }
    __syncthreads();
    if (ks == 0) {
#pragma unroll
        for (int p = 0; p < 4; ++p) {
            add2(acc[p][0], QS(tid, 2 * p));
            add2(acc[p][1], QS(tid, 2 * p + 1));
        }
#pragma unroll
        for (int cidx = 0; cidx < 2; ++cidx) {
            float b = __ldg(rb + cc + cidx);
#pragma unroll
            for (int p = 0; p < 4; ++p) {
                float lo, hi;
                unpk2(acc[p][cidx], lo, hi);
                HSE(rq + 2 * p,     cc + cidx) = tanhf(lo + b);
                HSE(rq + 2 * p + 1, cc + cidx) = tanhf(hi + b);
            }
        }
    }
    __syncthreads();

    // ---------------- GEMM2: hidden = h @ gate_W (16x64) --------------------
    {
        int r2 = tid >> 4;           // 0..15
        int j0 = (tid & 15) * 4;     // 0,4,..,60
        float ha[4];
#pragma unroll
        for (int j = 0; j < 4; ++j) ha[j] = __ldg(gb + j0 + j);
#pragma unroll 8
        for (int k = 0; k < 128; ++k) {
            float hv = HSE(r2, k);
            float4 g0 = *(const float4*)(gW + (size_t)k * 64 + j0);
            ha[0] = fmaf(hv, g0.x, ha[0]);
            ha[1] = fmaf(hv, g0.y, ha[1]);
            ha[2] = fmaf(hv, g0.z, ha[2]);
            ha[3] = fmaf(hv, g0.w, ha[3]);
        }
        int n = row0 + r2;
        float* ho = out + OFF_HID + (size_t)n * 64 + j0;
#pragma unroll
        for (int j = 0; j < 4; ++j) {
            HIDE(r2, j0 + j) = ha[j];
            ho[j] = ha[j];
        }
    }
    __syncthreads();

    // ---------------- Epilogue: top2 + routing + sparse expert path ---------
    if (tid < 128) {
        const int L = lane & 7;
        const int r = tid >> 3;
        const int n = row0 + r;

        float v1 = -INFINITY, v2 = -INFINITY;
        int   i1 = 0, i2 = 0;
#pragma unroll
        for (int j = 0; j < 8; ++j) {
            int idx = L * 8 + j;
            float v = HIDE(r, idx);
            if (v > v1) { v2 = v1; i2 = i1; v1 = v; i1 = idx; }
            else if (v > v2) { v2 = v; i2 = idx; }
        }
#pragma unroll
        for (int d = 1; d <= 4; d <<= 1) {
            float b1 = __shfl_down_sync(0xffffffffu, v1, d, 8);
            int  bi1 = __shfl_down_sync(0xffffffffu, i1, d, 8);
            float b2 = __shfl_down_sync(0xffffffffu, v2, d, 8);
            int  bi2 = __shfl_down_sync(0xffffffffu, i2, d, 8);
            if (b1 > v1) {
                if (v1 >= b2) { v2 = v1; i2 = i1; }
                else          { v2 = b2; i2 = bi2; }
                v1 = b1; i1 = bi1;
            } else if (b1 > v2) {
                v2 = b1; i2 = bi1;
            }
        }
        float rw1 = 0.f, rw2 = 0.f;
        if (L == 0) {
            float e2 = expf(v2 - v1);
            float inv = 1.f / (1.f + e2);
            rw1 = inv;
            rw2 = e2 * inv;
        }
        i1  = __shfl_sync(0xffffffffu, i1, 0, 8);
        i2  = __shfl_sync(0xffffffffu, i2, 0, 8);
        rw1 = __shfl_sync(0xffffffffu, rw1, 0, 8);
        rw2 = __shfl_sync(0xffffffffu, rw2, 0, 8);

#pragma unroll
        for (int j = 0; j < 8; ++j) {
            int idx = L * 8 + j;
            float val = (idx == i1) ? rw1 : ((idx == i2) ? rw2 : 0.f);
            out[OFF_RW1 + (size_t)n * 64 + idx] = val;
            out[OFF_RW2 + (size_t)n * 64 + idx] = val;
        }
        if (L == 0) {
            out[OFF_TK + (size_t)n * 2 + 0] = (float)i1;
            out[OFF_TK + (size_t)n * 2 + 1] = (float)i2;
        }

        float pred = 0.f;
#pragma unroll
        for (int s = 0; s < 2; ++s) {
            int sel  = s ? i2 : i1;
            float rw = s ? rw2 : rw1;
            int g = sel >> 3, f = sel & 7;

            const float4* ew4 = (const float4*)(eW + (size_t)(g * 8 + L) * 64);
            const float4* hd4 = (const float4*)&HIDE(r, 0);
            float s0 = 0.f, s1 = 0.f, s2 = 0.f, s3 = 0.f;
#pragma unroll
            for (int q = 0; q < 16; ++q) {
                float4 w4 = __ldg(ew4 + q);
                float4 x4 = hd4[q];
                s0 = fmaf(w4.x, x4.x, s0);
                s1 = fmaf(w4.y, x4.y, s1);
                s2 = fmaf(w4.z, x4.z, s2);
                s3 = fmaf(w4.w, x4.w, s3);
            }
            float eo = __ldg(eb + g * 8 + L) + (s0 + s1) + (s2 + s3);

            float qf = __ldg(wqb + g * 8 + L);
            float kf = __ldg(wkb + g * 8 + L);
            float vf = __ldg(wvb + g * 8 + L);
            const float* wqr = wq + (size_t)(g * 8 + L) * 8;
            const float* wkr = wk + (size_t)(g * 8 + L) * 8;
            const float* wvr = wv + (size_t)(g * 8 + L) * 8;
#pragma unroll
            for (int e = 0; e < 8; ++e) {
                float eoe = __shfl_sync(0xffffffffu, eo, e, 8);
                qf = fmaf(eoe, __ldg(wqr + e), qf);
                kf = fmaf(eoe, __ldg(wkr + e), kf);
                vf = fmaf(eoe, __ldg(wvr + e), vf);
            }
            float q8[8], k8[8], v8[8];
#pragma unroll
            for (int e = 0; e < 8; ++e) {
                q8[e] = __shfl_sync(0xffffffffu, qf, e, 8);
                k8[e] = __shfl_sync(0xffffffffu, kf, e, 8);
                v8[e] = __shfl_sync(0xffffffffu, vf, e, 8);
            }
            float s00 = 0.f, s01 = 0.f, s10 = 0.f, s11 = 0.f;
#pragma unroll
            for (int h = 0; h < 4; ++h) {
                float q0 = q8[2 * h], q1 = q8[2 * h + 1];
                float k0 = k8[2 * h], k1 = k8[2 * h + 1];
                s00 = fmaf(q0, k0, s00); s01 = fmaf(q0, k1, s01);
                s10 = fmaf(q1, k0, s10); s11 = fmaf(q1, k1, s11);
            }
            const float is2 = 0.70710678118654752440f;
            s00 *= is2; s01 *= is2; s10 *= is2; s11 *= is2;
            float m0 = fmaxf(s00, s01);
            float e00 = expf(s00 - m0), e01 = expf(s01 - m0);
            float n0 = 1.f / (e00 + e01);
            float a00 = e00 * n0, a01 = e01 * n0;
            float m1 = fmaxf(s10, s11);
            float e10 = expf(s10 - m1), e11 = expf(s11 - m1);
            float n1 = 1.f / (e10 + e11);
            float a10 = e10 * n1, a11 = e11 * n1;

            float att[8];
#pragma unroll
            for (int h = 0; h < 4; ++h) {
                att[2 * h]     = fmaf(a00, v8[2 * h], a01 * v8[2 * h + 1]);
                att[2 * h + 1] = fmaf(a10, v8[2 * h], a11 * v8[2 * h + 1]);
            }
            float aggf = __ldg(wob + g * 8 + f);
            const float* wor = wo + (size_t)(g * 8 + f) * 8;
#pragma unroll
            for (int e = 0; e < 8; ++e)
                aggf = fmaf(att[e], __ldg(wor + e), aggf);

            pred = fmaf(rw, aggf, pred);
        }
        if (L == 0) out[OFF_PRED + n] = pred;
    }
}

// ---------------------------------------------------------------------------
extern "C" void kernel_launch(void* const* d_in, const int* in_sizes, int n_in,
                              void* d_out, int out_size)
{
    const float* price = (const float*)d_in[0];
    const float* news  = (const float*)d_in[1];
    const float* mask  = (const float*)d_in[2];
    const float* rW    = (const float*)d_in[3];
    const float* rb    = (const float*)d_in[4];
    const float* gW    = (const float*)d_in[5];
    const float* gb    = (const float*)d_in[6];
    const float* eW    = (const float*)d_in[7];
    const float* eb    = (const float*)d_in[8];
    const float* wq    = (const float*)d_in[9];
    const float* wqb   = (const float*)d_in[10];
    const float* wk    = (const float*)d_in[11];
    const float* wkb   = (const float*)d_in[12];
    const float* wv    = (const float*)d_in[13];
    const float* wvb   = (const float*)d_in[14];
    const float* wo    = (const float*)d_in[15];
    const float* wob   = (const float*)d_in[16];
    float* out = (float*)d_out;

    k_all<<<NROWS / RPB, 256>>>(price, news, mask, rW, rb, gW, gb, eW, eb,
                                wq, wqb, wk, wkb, wv, wvb, wo, wob, out);
}

// round 16
// speedup vs baseline: 1.2170x; 1.2170x over previous
#include <cuda_runtime.h>
#include <math.h>

typedef unsigned long long ull;

// Shapes
#define NROWS 4096
#define RPB   16           // rows per block
#define CHUNKS 37          // 37 x 32 = 1184 k (1024 news | 158 price | 2 pad)
#define OFF_PRED 0
#define OFF_RW1  (NROWS)
#define OFF_HID  (NROWS + NROWS*64)
#define OFF_TK   (NROWS + 2*NROWS*64)
#define OFF_RW2  (NROWS + 2*NROWS*64 + NROWS*2)

// ---------------------------------------------------------------------------
// helpers
// ---------------------------------------------------------------------------
__device__ __forceinline__ ull pk2(float v) {
    ull r; asm("mov.b64 %0, {%1,%1};" : "=l"(r) : "f"(v)); return r;
}
__device__ __forceinline__ void fma2(ull& d, ull a, ull b) {
    asm("fma.rn.f32x2 %0, %1, %2, %0;" : "+l"(d) : "l"(a), "l"(b));
}
__device__ __forceinline__ void add2(ull& d, ull a) {
    asm("add.rn.f32x2 %0, %0, %1;" : "+l"(d) : "l"(a));
}
__device__ __forceinline__ void unpk2(ull v, float& lo, float& hi) {
    asm("mov.b64 {%0,%1}, %2;" : "=f"(lo), "=f"(hi) : "l"(v));
}
__device__ __forceinline__ unsigned s2u(const void* p) {
    unsigned a;
    asm("{ .reg .u64 t; cvta.to.shared.u64 t, %1; cvt.u32.u64 %0, t; }"
        : "=r"(a) : "l"(p));
    return a;
}
#define CPA16(dst, src) \
    asm volatile("cp.async.ca.shared.global [%0], [%1], 16;" \
                 :: "r"(dst), "l"(src))
#define CPA_COMMIT()  asm volatile("cp.async.commit_group;")
#define CPA_WAIT0()   asm volatile("cp.async.wait_group 0;" ::: "memory")
union F4U { float4 f; ull u[2]; };

// issue one 4-t sub-batch of the aggregation stream into dst[0..3]
__device__ __forceinline__ void load_sb(float4* dst, bool isNews,
                                        const float* nbase, const float* pbase,
                                        int kb, int d0, int b)
{
    if (isNews) {
#pragma unroll
        for (int t4 = 0; t4 < 4; ++t4)
            dst[t4] = *(const float4*)(nbase + (size_t)(b * 4 + t4) * 1024 + kb);
    } else {
#pragma unroll
        for (int t4 = 0; t4 < 4; ++t4) {
            const float* pr = pbase + (size_t)(b * 4 + t4) * 158 + d0;
            float2 lo = *(const float2*)pr;          // d0 <= 156 always valid
            float2 hi = (d0 + 4 <= 158) ? *(const float2*)(pr + 2)
                                        : make_float2(0.f, 0.f);
            dst[t4] = make_float4(lo.x, lo.y, hi.x, hi.y);
        }
    }
}

// ---------------------------------------------------------------------------
// Single fused kernel. 256 blocks x 256 threads, 16 rows/block, 2 CTAs/SM.
// Phase 1: aggregation (LDG.128 t-split, 3-slot ring with cross-chunk issue)
//          overlapped with k-split-2 router GEMM; W via cp.async.
// Phase 2 (smem-aliased): cross-warp combine, tanh, gate GEMM, top2, experts.
// ---------------------------------------------------------------------------
__global__ __launch_bounds__(256, 2) void k_all(
    const float* __restrict__ price, const float* __restrict__ news,
    const float* __restrict__ mask,  const float* __restrict__ rW,
    const float* __restrict__ rb,
    const float* __restrict__ gW,  const float* __restrict__ gb,
    const float* __restrict__ eW,  const float* __restrict__ eb,
    const float* __restrict__ wq,  const float* __restrict__ wqb,
    const float* __restrict__ wk,  const float* __restrict__ wkb,
    const float* __restrict__ wv,  const float* __restrict__ wvb,
    const float* __restrict__ wo,  const float* __restrict__ wob,
    float* __restrict__ out)
{
    __shared__ __align__(16) float Ws[2][32][128];   // 32 KB (aliased later)
    __shared__ __align__(16) float Xs[2][32][20];    // 5 KB (pitch 20)
    __shared__ __align__(16) float mw[RPB][33];      // mask weights
    __shared__ __align__(16) float4 Ps[RPB][8];      // agg t-split partials

    // phase-2 aliases inside Ws
    float* hP   = &Ws[0][0][0];                      // h_s  [16][132]
    float* hidP = hP + 16 * 132;                     // hid_s[16][68]
    ull*   QsP  = (ull*)((char*)&Ws[0][0][0] + 16384);  // [128][8] GEMM parts
#define HSE(r,c)  hP[(r) * 132 + (c)]
#define HIDE(r,c) hidP[(r) * 68 + (c)]
#define QS(t,i)   QsP[(t) * 8 + (i)]

    const int tid  = threadIdx.x;
    const int lane = tid & 31;
    const int wid  = tid >> 5;
    const int row0 = blockIdx.x * RPB;

    // ---- mask weights -------------------------------------------------------
    if (tid < RPB) {
        const float* mr = mask + (size_t)(row0 + tid) * 32;
        float s = 0.f;
#pragma unroll
        for (int t = 0; t < 32; ++t) s += __ldg(mr + t);
        float inv = 1.f / fmaxf(s, 1e-6f);
#pragma unroll
        for (int t = 0; t < 32; ++t) mw[tid][t] = __ldg(mr + t) * inv;
    }

    // aggregation mapping: thread -> t-half th, row ar, col-quad aj
    const int th = tid >> 7;            // 0: t 0-15, 1: t 16-31
    const int ar = (tid >> 3) & 15;
    const int aj = tid & 7;
    const float* nbase = news  + ((size_t)(row0 + ar) * 32 + th * 16) * 1024
                               + aj * 4;
    const float* pbase = price + ((size_t)(row0 + ar) * 32 + th * 16) * 158;
    // W loader mapping (cp.async)
    const int wkk = tid >> 3;
    const int wcc = (tid & 7) * 16;
    unsigned wdst[2];
    wdst[0] = s2u(&Ws[0][wkk][wcc]);
    wdst[1] = s2u(&Ws[1][wkk][wcc]);
    // GEMM mapping: ks = k-half, warp = 8 rows x 64 cols
    const int ks = wid >> 2;                         // 0 or 1
    const int hw = wid & 3;
    const int rq = (hw & 1) << 3;                    // 0 or 8
    const int cc = ((hw >> 1) << 6) + (lane << 1);   // col pair base

    // acc[p][c]: rows (rq+2p, rq+2p+1) packed, col cc+c
    ull acc[4][2];
#pragma unroll
    for (int p = 0; p < 4; ++p) { acc[p][0] = 0ull; acc[p][1] = 0ull; }

    // ---- W chunk 0 via cp.async --------------------------------------------
    {
        const float* wp = rW + (size_t)(wkk + 158) * 128 + wcc;
#pragma unroll
        for (int q = 0; q < 4; ++q) CPA16(wdst[0] + 16 * q, wp + 4 * q);
        CPA_COMMIT();
    }
    __syncthreads();   // mask weights visible

    // ---- prologue: aggregate + store chunk 0 (news) ------------------------
    {
        float4 a = make_float4(0.f, 0.f, 0.f, 0.f);
#pragma unroll
        for (int t = 0; t < 16; ++t) {
            float4 nv0 = *(const float4*)(nbase + (size_t)t * 1024);
            float w = mw[ar][th * 16 + t];
            a.x = fmaf(w, nv0.x, a.x); a.y = fmaf(w, nv0.y, a.y);
            a.z = fmaf(w, nv0.z, a.z); a.w = fmaf(w, nv0.w, a.w);
        }
        if (th == 1) Ps[ar][aj] = a;
        __syncthreads();
        if (th == 0) {
            float4 p = Ps[ar][aj];
            Xs[0][aj * 4 + 0][ar] = a.x + p.x;
            Xs[0][aj * 4 + 1][ar] = a.y + p.y;
            Xs[0][aj * 4 + 2][ar] = a.z + p.z;
            Xs[0][aj * 4 + 3][ar] = a.w + p.w;
        }
    }

    // 3-slot ring; pre-issue batches 0,1 for chunk 1 (aggregated during c=0)
    float4 nv[3][4];
    load_sb(nv[0], true, nbase, pbase, 32, 32 - 1024 + aj * 4, 0);
    load_sb(nv[1], true, nbase, pbase, 32, 32 - 1024 + aj * 4, 1);

    CPA_WAIT0();
    __syncthreads();

    // ---- main loop ----------------------------------------------------------
#pragma unroll 1
    for (int c = 0; c < CHUNKS; ++c) {
        const int  s      = c & 1;
        const bool more   = (c + 1 < CHUNKS);
        const bool isNews = (c + 1 < 32);
        const int  kb     = (c + 1) * 32;
        const int  d0     = kb - 1024 + aj * 4;

        // stage W chunk c+1 via cp.async
        if (more) {
            int k = kb + wkk;
            if (k < 1182) {
                int wr = (k < 1024) ? (k + 158) : (k - 1024);
                const float* wp = rW + (size_t)wr * 128 + wcc;
#pragma unroll
                for (int q = 0; q < 4; ++q)
                    CPA16(wdst[1 - s] + 16 * q, wp + 4 * q);
            } else {
                float4 z = make_float4(0.f, 0.f, 0.f, 0.f);
#pragma unroll
                for (int q = 0; q < 4; ++q)
                    *(float4*)&Ws[1 - s][wkk][wcc + 4 * q] = z;
            }
            CPA_COMMIT();
        }

        float4 a = make_float4(0.f, 0.f, 0.f, 0.f);

#pragma unroll
        for (int b = 0; b < 4; ++b) {
            // issue batch b+2 into ring slot (b+2)%3
            if (more && b + 2 < 4)
                load_sb(nv[(b + 2) % 3], isNews, nbase, pbase, kb, d0, b + 2);
            // GEMM: this warp's k-quarter of the batch window
#pragma unroll
            for (int kk = 0; kk < 4; ++kk) {
                const int k = b * 8 + ks * 4 + kk;
                F4U x0, x1;
                x0.f = *(const float4*)&Xs[s][k][rq];        // rows rq..rq+3
                x1.f = *(const float4*)&Xs[s][k][rq + 4];    // rows rq+4..rq+7
                float2 wv2 = *(const float2*)&Ws[s][k][cc];  // 2 cols
                ull w0 = pk2(wv2.x), w1 = pk2(wv2.y);
                fma2(acc[0][0], x0.u[0], w0); fma2(acc[0][1], x0.u[0], w1);
                fma2(acc[1][0], x0.u[1], w0); fma2(acc[1][1], x0.u[1], w1);
                fma2(acc[2][0], x1.u[0], w0); fma2(acc[2][1], x1.u[0], w1);
                fma2(acc[3][0], x1.u[1], w0); fma2(acc[3][1], x1.u[1], w1);
            }
            // fold batch b from ring slot b%3
            if (more) {
                float4* cur = nv[b % 3];
                if (isNews) {
#pragma unroll
                    for (int t4 = 0; t4 < 4; ++t4) {
                        float w = mw[ar][th * 16 + b * 4 + t4];
                        a.x = fmaf(w, cur[t4].x, a.x);
                        a.y = fmaf(w, cur[t4].y, a.y);
                        a.z = fmaf(w, cur[t4].z, a.z);
                        a.w = fmaf(w, cur[t4].w, a.w);
                    }
                } else {
#pragma unroll
                    for (int t4 = 0; t4 < 4; ++t4) {
                        a.x += cur[t4].x; a.y += cur[t4].y;
                        a.z += cur[t4].z; a.w += cur[t4].w;
                    }
                }
            }
        }

        // pre-issue batches 0,1 of chunk c+2 BEFORE the combine+barrier:
        // their folds (early next iteration) get the barrier window for free.
        if (c + 2 < CHUNKS) {
            const bool isNews2 = (c + 2 < 32);
            const int  kb2 = (c + 2) * 32;
            const int  d02 = kb2 - 1024 + aj * 4;
            load_sb(nv[0], isNews2, nbase, pbase, kb2, d02, 0);
            load_sb(nv[1], isNews2, nbase, pbase, kb2, d02, 1);
        }

        if (more) {
            if (th == 1) Ps[ar][aj] = a;
            __syncthreads();
            if (th == 0) {
                const float sc = isNews ? 1.f : (1.f / 32.f);
                float4 p = Ps[ar][aj];
                Xs[1 - s][aj * 4 + 0][ar] = (a.x + p.x) * sc;
                Xs[1 - s][aj * 4 + 1][ar] = (a.y + p.y) * sc;
                Xs[1 - s][aj * 4 + 2][ar] = (a.z + p.z) * sc;
                Xs[1 - s][aj * 4 + 3][ar] = (a.w + p.w) * sc;
            }
            CPA_WAIT0();
        }
        __syncthreads();
    }

    // ---- cross-warp k-combine, bias + tanh -> h_s ---------------------------
    if (ks == 1) {
#pragma unroll
        for (int p = 0; p < 4; ++p) {
            QS(tid - 128, 2 * p)     = acc[p][0];
            QS(tid - 128, 2 * p + 1) = acc[p][1];
        }
    }
    __syncthreads();
    if (ks == 0) {
#pragma unroll
        for (int p = 0; p < 4; ++p) {
            add2(acc[p][0], QS(tid, 2 * p));
            add2(acc[p][1], QS(tid, 2 * p + 1));
        }
#pragma unroll
        for (int cidx = 0; cidx < 2; ++cidx) {
            float b = __ldg(rb + cc + cidx);
#pragma unroll
            for (int p = 0; p < 4; ++p) {
                float lo, hi;
                unpk2(acc[p][cidx], lo, hi);
                HSE(rq + 2 * p,     cc + cidx) = tanhf(lo + b);
                HSE(rq + 2 * p + 1, cc + cidx) = tanhf(hi + b);
            }
        }
    }
    __syncthreads();

    // ---------------- GEMM2: hidden = h @ gate_W (16x64) --------------------
    {
        int r2 = tid >> 4;           // 0..15
        int j0 = (tid & 15) * 4;     // 0,4,..,60
        float ha[4];
#pragma unroll
        for (int j = 0; j < 4; ++j) ha[j] = __ldg(gb + j0 + j);
#pragma unroll 8
        for (int k = 0; k < 128; ++k) {
            float hv = HSE(r2, k);
            float4 g0 = *(const float4*)(gW + (size_t)k * 64 + j0);
            ha[0] = fmaf(hv, g0.x, ha[0]);
            ha[1] = fmaf(hv, g0.y, ha[1]);
            ha[2] = fmaf(hv, g0.z, ha[2]);
            ha[3] = fmaf(hv, g0.w, ha[3]);
        }
        int n = row0 + r2;
        float* ho = out + OFF_HID + (size_t)n * 64 + j0;
#pragma unroll
        for (int j = 0; j < 4; ++j) {
            HIDE(r2, j0 + j) = ha[j];
            ho[j] = ha[j];
        }
    }
    __syncthreads();

    // ---------------- Epilogue: top2 + routing + sparse expert path ---------
    if (tid < 128) {
        const int L = lane & 7;
        const int r = tid >> 3;
        const int n = row0 + r;

        float v1 = -INFINITY, v2 = -INFINITY;
        int   i1 = 0, i2 = 0;
#pragma unroll
        for (int j = 0; j < 8; ++j) {
            int idx = L * 8 + j;
            float v = HIDE(r, idx);
            if (v > v1) { v2 = v1; i2 = i1; v1 = v; i1 = idx; }
            else if (v > v2) { v2 = v; i2 = idx; }
        }
#pragma unroll
        for (int d = 1; d <= 4; d <<= 1) {
            float b1 = __shfl_down_sync(0xffffffffu, v1, d, 8);
            int  bi1 = __shfl_down_sync(0xffffffffu, i1, d, 8);
            float b2 = __shfl_down_sync(0xffffffffu, v2, d, 8);
            int  bi2 = __shfl_down_sync(0xffffffffu, i2, d, 8);
            if (b1 > v1) {
                if (v1 >= b2) { v2 = v1; i2 = i1; }
                else          { v2 = b2; i2 = bi2; }
                v1 = b1; i1 = bi1;
            } else if (b1 > v2) {
                v2 = b1; i2 = bi1;
            }
        }
        float rw1 = 0.f, rw2 = 0.f;
        if (L == 0) {
            float e2 = expf(v2 - v1);
            float inv = 1.f / (1.f + e2);
            rw1 = inv;
            rw2 = e2 * inv;
        }
        i1  = __shfl_sync(0xffffffffu, i1, 0, 8);
        i2  = __shfl_sync(0xffffffffu, i2, 0, 8);
        rw1 = __shfl_sync(0xffffffffu, rw1, 0, 8);
        rw2 = __shfl_sync(0xffffffffu, rw2, 0, 8);

#pragma unroll
        for (int j = 0; j < 8; ++j) {
            int idx = L * 8 + j;
            float val = (idx == i1) ? rw1 : ((idx == i2) ? rw2 : 0.f);
            out[OFF_RW1 + (size_t)n * 64 + idx] = val;
            out[OFF_RW2 + (size_t)n * 64 + idx] = val;
        }
        if (L == 0) {
            out[OFF_TK + (size_t)n * 2 + 0] = (float)i1;
            out[OFF_TK + (size_t)n * 2 + 1] = (float)i2;
        }

        float pred = 0.f;
#pragma unroll
        for (int s = 0; s < 2; ++s) {
            int sel  = s ? i2 : i1;
            float rw = s ? rw2 : rw1;
            int g = sel >> 3, f = sel & 7;

            const float4* ew4 = (const float4*)(eW + (size_t)(g * 8 + L) * 64);
            const float4* hd4 = (const float4*)&HIDE(r, 0);
            float s0 = 0.f, s1 = 0.f, s2 = 0.f, s3 = 0.f;
#pragma unroll
            for (int q = 0; q < 16; ++q) {
                float4 w4 = __ldg(ew4 + q);
                float4 x4 = hd4[q];
                s0 = fmaf(w4.x, x4.x, s0);
                s1 = fmaf(w4.y, x4.y, s1);
                s2 = fmaf(w4.z, x4.z, s2);
                s3 = fmaf(w4.w, x4.w, s3);
            }
            float eo = __ldg(eb + g * 8 + L) + (s0 + s1) + (s2 + s3);

            float qf = __ldg(wqb + g * 8 + L);
            float kf = __ldg(wkb + g * 8 + L);
            float vf = __ldg(wvb + g * 8 + L);
            const float* wqr = wq + (size_t)(g * 8 + L) * 8;
            const float* wkr = wk + (size_t)(g * 8 + L) * 8;
            const float* wvr = wv + (size_t)(g * 8 + L) * 8;
#pragma unroll
            for (int e = 0; e < 8; ++e) {
                float eoe = __shfl_sync(0xffffffffu, eo, e, 8);
                qf = fmaf(eoe, __ldg(wqr + e), qf);
                kf = fmaf(eoe, __ldg(wkr + e), kf);
                vf = fmaf(eoe, __ldg(wvr + e), vf);
            }
            float q8[8], k8[8], v8[8];
#pragma unroll
            for (int e = 0; e < 8; ++e) {
                q8[e] = __shfl_sync(0xffffffffu, qf, e, 8);
                k8[e] = __shfl_sync(0xffffffffu, kf, e, 8);
                v8[e] = __shfl_sync(0xffffffffu, vf, e, 8);
            }
            float s00 = 0.f, s01 = 0.f, s10 = 0.f, s11 = 0.f;
#pragma unroll
            for (int h = 0; h < 4; ++h) {
                float q0 = q8[2 * h], q1 = q8[2 * h + 1];
                float k0 = k8[2 * h], k1 = k8[2 * h + 1];
                s00 = fmaf(q0, k0, s00); s01 = fmaf(q0, k1, s01);
                s10 = fmaf(q1, k0, s10); s11 = fmaf(q1, k1, s11);
            }
            const float is2 = 0.70710678118654752440f;
            s00 *= is2; s01 *= is2; s10 *= is2; s11 *= is2;
            float m0 = fmaxf(s00, s01);
            float e00 = expf(s00 - m0), e01 = expf(s01 - m0);
            float n0 = 1.f / (e00 + e01);
            float a00 = e00 * n0, a01 = e01 * n0;
            float m1 = fmaxf(s10, s11);
            float e10 = expf(s10 - m1), e11 = expf(s11 - m1);
            float n1 = 1.f / (e10 + e11);
            float a10 = e10 * n1, a11 = e11 * n1;

            float att[8];
#pragma unroll
            for (int h = 0; h < 4; ++h) {
                att[2 * h]     = fmaf(a00, v8[2 * h], a01 * v8[2 * h + 1]);
                att[2 * h + 1] = fmaf(a10, v8[2 * h], a11 * v8[2 * h + 1]);
            }
            float aggf = __ldg(wob + g * 8 + f);
            const float* wor = wo + (size_t)(g * 8 + f) * 8;
#pragma unroll
            for (int e = 0; e < 8; ++e)
                aggf = fmaf(att[e], __ldg(wor + e), aggf);

            pred = fmaf(rw, aggf, pred);
        }
        if (L == 0) out[OFF_PRED + n] = pred;
    }
}

// ---------------------------------------------------------------------------
extern "C" void kernel_launch(void* const* d_in, const int* in_sizes, int n_in,
                              void* d_out, int out_size)
{
    const float* price = (const float*)d_in[0];
    const float* news  = (const float*)d_in[1];
    const float* mask  = (const float*)d_in[2];
    const float* rW    = (const float*)d_in[3];
    const float* rb    = (const float*)d_in[4];
    const float* gW    = (const float*)d_in[5];
    const float* gb    = (const float*)d_in[6];
    const float* eW    = (const float*)d_in[7];
    const float* eb    = (const float*)d_in[8];
    const float* wq    = (const float*)d_in[9];
    const float* wqb   = (const float*)d_in[10];
    const float* wk    = (const float*)d_in[11];
    const float* wkb   = (const float*)d_in[12];
    const float* wv    = (const float*)d_in[13];
    const float* wvb   = (const float*)d_in[14];
    const float* wo    = (const float*)d_in[15];
    const float* wob   = (const float*)d_in[16];
    float* out = (float*)d_out;

    k_all<<<NROWS / RPB, 256>>>(price, news, mask, rW, rb, gW, gb, eW, eb,
                                wq, wqb, wk, wkb, wv, wvb, wo, wob, out);
}